// round 1
// baseline (speedup 1.0000x reference)
#include <cuda_runtime.h>
#include <cstdint>

// Problem shapes (fixed by the dataset)
#define NB   64      // batches
#define HW   1024    // tokens per batch (32*32)
#define CC   512     // channels
#define EE   5       // experts
#define HID  2048    // hidden

// ---------------- device scratch (no allocations allowed) ----------------
__device__ float g_xg[NB * CC];
__device__ int   g_expert[NB];
__device__ float g_h[(size_t)NB * HW * HID];   // 512 MB fp32 scratch for gelu(x@W1+b1)

// ---------------- helpers ----------------
__device__ __forceinline__ float to_tf32(float x) {
    float r; asm("cvt.rna.tf32.f32 %0, %1;" : "=f"(r) : "f"(x)); return r;
}

__device__ __forceinline__ float gelu_exact(float v) {
    // gelu(approximate=False) = 0.5 * v * (1 + erf(v / sqrt(2)))
    return 0.5f * v * (1.0f + erff(v * 0.70710678118654752440f));
}

__device__ __forceinline__ void mma_tf32_16x8x8(float* d, const uint32_t* a, const uint32_t* b) {
    asm volatile(
        "mma.sync.aligned.m16n8k8.row.col.f32.tf32.tf32.f32 "
        "{%0,%1,%2,%3}, {%4,%5,%6,%7}, {%8,%9}, {%0,%1,%2,%3};\n"
        : "+f"(d[0]), "+f"(d[1]), "+f"(d[2]), "+f"(d[3])
        : "r"(a[0]), "r"(a[1]), "r"(a[2]), "r"(a[3]),
          "r"(b[0]), "r"(b[1]));
}

// ---------------- kernel 1: per-batch channel means ----------------
__global__ void xg_kernel(const float* __restrict__ x) {
    int b = blockIdx.x;
    int c = threadIdx.x;                    // 512 threads, one per channel
    const float* p = x + (size_t)b * HW * CC + c;
    float s = 0.0f;
    #pragma unroll 8
    for (int i = 0; i < HW; ++i) s += p[(size_t)i * CC];
    g_xg[b * CC + c] = s * (1.0f / (float)HW);
}

// ---------------- kernel 2: gating (argmax) + aux loss ----------------
// K=1: softmax over one logit == 1.0, so gates are exactly 1.0 and
// importance == load == per-expert counts. Clip(+-50) cannot change the argmax
// here (|logits| << 1 for this data distribution).
__global__ void gate_kernel(const float* __restrict__ wg, float* __restrict__ loss_out) {
    __shared__ int sh_e[NB];
    int b = threadIdx.x;
    if (b < NB) {
        float best = -3.4e38f; int bi = 0;
        for (int e = 0; e < EE; ++e) {
            float s = 0.0f;
            for (int c = 0; c < CC; ++c) s += g_xg[b * CC + c] * wg[c * EE + e];
            if (s > best) { best = s; bi = e; }   // strict > == lowest index on tie (top_k semantics)
        }
        sh_e[b] = bi;
        g_expert[b] = bi;
    }
    __syncthreads();
    if (b == 0) {
        float cnt[EE] = {0.f, 0.f, 0.f, 0.f, 0.f};
        for (int i = 0; i < NB; ++i) cnt[sh_e[i]] += 1.0f;
        float m = 0.0f;
        for (int e = 0; e < EE; ++e) m += cnt[e];
        m /= (float)EE;
        float var = 0.0f;
        for (int e = 0; e < EE; ++e) { float d = cnt[e] - m; var += d * d; }
        var /= (float)(EE - 1);                      // ddof=1
        float cv = (fabsf(m) < 1e-10f) ? 0.0f : var / (m * m + 1e-10f);
        float loss = 2.0f * cv;                      // importance == load
        if (loss > 1000.0f) loss = 1000.0f;
        *loss_out = loss;
    }
}

// ---------------- TF32 tensor-core GEMM, per-batch expert weights ----------------
// C[b] (MxN) = op( A[b] (MxK) @ W[expert[b]] (KxN) + bias[expert[b]] )
// CTA tile 128x128, K-chunk 32, 8 warps (2x4), warp tile 64x32, frag m16n8k8.
// All dims divide exactly (M=1024, N in {2048,512}, K in {512,2048}) -> no predicates.
template <bool GELU, bool A_IS_SCRATCH, bool C_IS_SCRATCH>
__global__ __launch_bounds__(256, 2)
void gemm_tf32(const float* __restrict__ Ain, const float* __restrict__ Wbase,
               const float* __restrict__ biasbase, float* __restrict__ Cout,
               int M, int N, int K)
{
    // Paddings: As stride 36 words -> frag-A banks 4r+c (conflict-free)
    //           Bs stride 136 words -> frag-B banks 8k+n (conflict-free)
    __shared__ float As[128][36];
    __shared__ float Bs[32][136];

    const int b  = blockIdx.z;
    const int e  = g_expert[b];
    const float* A    = (A_IS_SCRATCH ? g_h : Ain) + (size_t)b * M * K;
    const float* Bm   = Wbase + (size_t)e * K * N;
    const float* bias = biasbase + (size_t)e * N;
    float* Cp         = (C_IS_SCRATCH ? g_h : Cout) + (size_t)b * M * N;

    const int m0 = blockIdx.y * 128, n0 = blockIdx.x * 128;
    const int tid = threadIdx.x, lane = tid & 31, warp = tid >> 5;
    const int wm = warp >> 2, wn = warp & 3;       // 2 x 4 warp grid
    const int r  = lane >> 2, cA = lane & 3;       // fragment row / k-col

    float acc[4][4][4];
    #pragma unroll
    for (int i = 0; i < 4; ++i)
        #pragma unroll
        for (int j = 0; j < 4; ++j)
            #pragma unroll
            for (int q = 0; q < 4; ++q) acc[i][j][q] = 0.0f;

    const int nkt = K >> 5;
    for (int kt = 0; kt < nkt; ++kt) {
        // stage A tile 128 x 32 (row-major m,k), tf32-rounded
        #pragma unroll
        for (int i = 0; i < 4; ++i) {
            int idx = tid + i * 256;
            int row = idx >> 3, kv = (idx & 7) << 2;
            float4 v = *reinterpret_cast<const float4*>(
                &A[(size_t)(m0 + row) * K + kt * 32 + kv]);
            v.x = to_tf32(v.x); v.y = to_tf32(v.y);
            v.z = to_tf32(v.z); v.w = to_tf32(v.w);
            *reinterpret_cast<float4*>(&As[row][kv]) = v;
        }
        // stage B tile 32 x 128 (row-major k,n), tf32-rounded
        #pragma unroll
        for (int i = 0; i < 4; ++i) {
            int idx = tid + i * 256;
            int krow = idx >> 5, nv = (idx & 31) << 2;
            float4 v = *reinterpret_cast<const float4*>(
                &Bm[(size_t)(kt * 32 + krow) * N + n0 + nv]);
            v.x = to_tf32(v.x); v.y = to_tf32(v.y);
            v.z = to_tf32(v.z); v.w = to_tf32(v.w);
            *reinterpret_cast<float4*>(&Bs[krow][nv]) = v;
        }
        __syncthreads();

        #pragma unroll
        for (int k8 = 0; k8 < 4; ++k8) {
            const int kb = k8 * 8;
            uint32_t af[4][4], bf[4][2];
            #pragma unroll
            for (int i = 0; i < 4; ++i) {
                int m = wm * 64 + i * 16;
                af[i][0] = __float_as_uint(As[m + r    ][kb + cA    ]);
                af[i][1] = __float_as_uint(As[m + r + 8][kb + cA    ]);
                af[i][2] = __float_as_uint(As[m + r    ][kb + cA + 4]);
                af[i][3] = __float_as_uint(As[m + r + 8][kb + cA + 4]);
            }
            #pragma unroll
            for (int j = 0; j < 4; ++j) {
                int n = wn * 32 + j * 8 + r;       // b-frag: k = lane%4, n = lane/4
                bf[j][0] = __float_as_uint(Bs[kb + cA    ][n]);
                bf[j][1] = __float_as_uint(Bs[kb + cA + 4][n]);
            }
            #pragma unroll
            for (int i = 0; i < 4; ++i)
                #pragma unroll
                for (int j = 0; j < 4; ++j)
                    mma_tf32_16x8x8(acc[i][j], af[i], bf[j]);
        }
        __syncthreads();
    }

    // epilogue: +bias (and gelu for GEMM1), float2 stores
    #pragma unroll
    for (int j = 0; j < 4; ++j) {
        int col = n0 + wn * 32 + j * 8 + cA * 2;
        float bv0 = bias[col], bv1 = bias[col + 1];
        #pragma unroll
        for (int i = 0; i < 4; ++i) {
            int row0 = m0 + wm * 64 + i * 16 + r;
            float v00 = acc[i][j][0] + bv0, v01 = acc[i][j][1] + bv1;
            float v10 = acc[i][j][2] + bv0, v11 = acc[i][j][3] + bv1;
            if (GELU) {
                v00 = gelu_exact(v00); v01 = gelu_exact(v01);
                v10 = gelu_exact(v10); v11 = gelu_exact(v11);
            }
            *reinterpret_cast<float2*>(&Cp[(size_t)row0 * N + col])       = make_float2(v00, v01);
            *reinterpret_cast<float2*>(&Cp[(size_t)(row0 + 8) * N + col]) = make_float2(v10, v11);
        }
    }
}

// ---------------- launch ----------------
extern "C" void kernel_launch(void* const* d_in, const int* in_sizes, int n_in,
                              void* d_out, int out_size)
{
    const float* x  = (const float*)d_in[0];   // (64,32,32,512)
    const float* wg = (const float*)d_in[1];   // (512,5)
    const float* W1 = (const float*)d_in[2];   // (5,512,2048)
    const float* b1 = (const float*)d_in[3];   // (5,2048)
    const float* W2 = (const float*)d_in[4];   // (5,2048,512)
    const float* b2 = (const float*)d_in[5];   // (5,512)
    float* out = (float*)d_out;                // y (64*1024*512) then loss (1)

    // 1) per-batch means
    xg_kernel<<<NB, CC>>>(x);

    // 2) gating + loss (loss is last element of out)
    gate_kernel<<<1, NB>>>(wg, out + (size_t)out_size - 1);

    // 3) h = gelu(x @ W1[e] + b1[e])  -> g_h
    dim3 g1(HID / 128, HW / 128, NB);   // (16, 8, 64)
    gemm_tf32<true, false, true><<<g1, 256>>>(x, W1, b1, nullptr, HW, HID, CC);

    // 4) y = h @ W2[e] + b2[e]        -> out
    dim3 g2(CC / 128, HW / 128, NB);    // (4, 8, 64)
    gemm_tf32<false, true, false><<<g2, 256>>>(nullptr, W2, b2, out, HW, CC, HID);
}

// round 9
// speedup vs baseline: 1.8909x; 1.8909x over previous
#include <cuda_runtime.h>
#include <cuda_fp16.h>
#include <cstdint>

// Problem shapes (fixed by the dataset)
#define NB   64      // batches
#define HW   1024    // tokens per batch (32*32)
#define CC   512     // channels
#define EE   5       // experts
#define HID  2048    // hidden

// ---------------- device scratch (no allocations allowed) ----------------
__device__ float  g_xg[NB * CC];
__device__ int    g_expert[NB];
__device__ __half g_x16[(size_t)NB * HW * CC];     // fp16 copy of x       (64 MB)
__device__ __half g_w116[(size_t)EE * CC * HID];   // fp16 copy of W1      (10.5 MB)
__device__ __half g_w216[(size_t)EE * HID * CC];   // fp16 copy of W2      (10.5 MB)
__device__ __half g_h16[(size_t)NB * HW * HID];    // fp16 h = gelu(xW1+b) (256 MB)

// ---------------- PTX helpers ----------------
__device__ __forceinline__ uint32_t smem_u32(const void* p) {
    uint32_t a;
    asm("{ .reg .u64 t; cvta.to.shared.u64 t, %1; cvt.u32.u64 %0, t; }" : "=r"(a) : "l"(p));
    return a;
}

__device__ __forceinline__ void cp_async16(uint32_t dst, const void* src) {
    asm volatile("cp.async.cg.shared.global [%0], [%1], 16;\n" :: "r"(dst), "l"(src));
}
#define CP_COMMIT() asm volatile("cp.async.commit_group;\n" ::: "memory")
#define CP_WAIT2()  asm volatile("cp.async.wait_group 2;\n" ::: "memory")

__device__ __forceinline__ void ldm_x4(uint32_t* r, uint32_t addr) {
    asm volatile("ldmatrix.sync.aligned.m8n8.x4.shared.b16 {%0,%1,%2,%3}, [%4];\n"
        : "=r"(r[0]), "=r"(r[1]), "=r"(r[2]), "=r"(r[3]) : "r"(addr));
}
__device__ __forceinline__ void ldm_x4_t(uint32_t* r, uint32_t addr) {
    asm volatile("ldmatrix.sync.aligned.m8n8.x4.trans.shared.b16 {%0,%1,%2,%3}, [%4];\n"
        : "=r"(r[0]), "=r"(r[1]), "=r"(r[2]), "=r"(r[3]) : "r"(addr));
}
__device__ __forceinline__ void mma_f16(float* d, const uint32_t* a, const uint32_t* b) {
    asm volatile(
        "mma.sync.aligned.m16n8k16.row.col.f32.f16.f16.f32 "
        "{%0,%1,%2,%3}, {%4,%5,%6,%7}, {%8,%9}, {%0,%1,%2,%3};\n"
        : "+f"(d[0]), "+f"(d[1]), "+f"(d[2]), "+f"(d[3])
        : "r"(a[0]), "r"(a[1]), "r"(a[2]), "r"(a[3]), "r"(b[0]), "r"(b[1]));
}

__device__ __forceinline__ float gelu_exact(float v) {
    return 0.5f * v * (1.0f + erff(v * 0.70710678118654752440f));
}

// ---------------- kernel: per-batch channel means (fp32 x, exact) ----------------
__global__ void xg_kernel(const float* __restrict__ x) {
    int b = blockIdx.x;
    int c = threadIdx.x;
    const float* p = x + (size_t)b * HW * CC + c;
    float s = 0.0f;
    #pragma unroll 8
    for (int i = 0; i < HW; ++i) s += p[(size_t)i * CC];
    g_xg[b * CC + c] = s * (1.0f / (float)HW);
}

// ---------------- kernel: gating (argmax) + aux loss ----------------
// K=1: softmax over one logit == 1.0; importance == load == per-expert counts.
__global__ void gate_kernel(const float* __restrict__ wg, float* __restrict__ loss_out) {
    __shared__ int sh_e[NB];
    int b = threadIdx.x;
    if (b < NB) {
        float best = -3.4e38f; int bi = 0;
        for (int e = 0; e < EE; ++e) {
            float s = 0.0f;
            for (int c = 0; c < CC; ++c) s += g_xg[b * CC + c] * wg[c * EE + e];
            if (s > best) { best = s; bi = e; }   // strict > == lowest-index tie-break (top_k)
        }
        sh_e[b] = bi;
        g_expert[b] = bi;
    }
    __syncthreads();
    if (b == 0) {
        float cnt[EE] = {0.f, 0.f, 0.f, 0.f, 0.f};
        for (int i = 0; i < NB; ++i) cnt[sh_e[i]] += 1.0f;
        float m = 0.0f;
        for (int e = 0; e < EE; ++e) m += cnt[e];
        m /= (float)EE;
        float var = 0.0f;
        for (int e = 0; e < EE; ++e) { float d = cnt[e] - m; var += d * d; }
        var /= (float)(EE - 1);                      // ddof=1
        float cv = (fabsf(m) < 1e-10f) ? 0.0f : var / (m * m + 1e-10f);
        float loss = 2.0f * cv;                      // importance == load
        if (loss > 1000.0f) loss = 1000.0f;
        *loss_out = loss;
    }
}

// ---------------- fp16 tensor-core GEMM with cp.async pipeline ----------------
// C[b] (MxN) = op( A[b] (MxK) @ W[expert[b]] (KxN) + bias[expert[b]] )
// CTA tile 128x128, 8 warps (2x4), warp tile 64x32, K-chunk 64, fragments m16n8k16.
// 3-stage cp.async pipeline (fp16 operands in gmem), ldmatrix fragment loads.
// NOTE: all __device__ arrays (g_x16/g_h16/g_w116/g_w216) are referenced ONLY
// inside device code — passing them as kernel args from host yields the host
// shadow address and faults (the R7 bug).
#define KC    64                 // K elements per chunk
#define ROWA  144                // A smem row bytes (64 halves + 8 pad halves)
#define ROWB  272                // B smem row bytes (128 halves + 8 pad halves)
#define ASZ   (128 * ROWA)       // 18432
#define BSZ   (KC * ROWB)        // 17408
#define STAGE (ASZ + BSZ)        // 35840
#define NSTG  3
#define SMEM_BYTES (NSTG * STAGE)   // 107520 -> 2 CTAs/SM = 215040 B

template <bool GELU, bool A_IS_SCR, bool C_IS_SCR>
__global__ __launch_bounds__(256, 2)
void gemm_fp16(const float* __restrict__ biasbase, float* __restrict__ Cout,
               int M, int N, int K)
{
    extern __shared__ char smem[];
    const uint32_t sbase = smem_u32(smem);

    const int b = blockIdx.z;
    const int e = g_expert[b];
    const __half* A    = (A_IS_SCR ? g_h16 : g_x16) + (size_t)b * M * K;
    const __half* Bm   = (C_IS_SCR ? g_w116 : g_w216) + (size_t)e * K * N;  // W1 for GEMM1, W2 for GEMM2
    const float*  bias = biasbase + (size_t)e * N;

    const int m0 = blockIdx.y * 128, n0 = blockIdx.x * 128;
    const int tid = threadIdx.x, lane = tid & 31, warp = tid >> 5;
    const int wm = warp >> 2, wn = warp & 3;          // 2x4 warp grid, warp tile 64x32

    const int nkt = K / KC;

    // stage chunk kt into buffer s (8 x cp.async 16B per thread)
    auto issue = [&](int kt, int s) {
        uint32_t as = sbase + s * STAGE;
        uint32_t bs = as + ASZ;
        #pragma unroll
        for (int i = 0; i < 4; ++i) {                 // A: 128 rows x 8 chunks
            int idx = tid + i * 256;
            int row = idx >> 3, cg = idx & 7;
            cp_async16(as + row * ROWA + cg * 16,
                       A + (size_t)(m0 + row) * K + kt * KC + cg * 8);
        }
        #pragma unroll
        for (int i = 0; i < 4; ++i) {                 // B: 64 k-rows x 16 chunks
            int idx = tid + i * 256;
            int row = idx >> 4, cg = idx & 15;
            cp_async16(bs + row * ROWB + cg * 16,
                       Bm + (size_t)(kt * KC + row) * N + n0 + cg * 8);
        }
    };

    float acc[4][4][4];
    #pragma unroll
    for (int i = 0; i < 4; ++i)
        #pragma unroll
        for (int j = 0; j < 4; ++j)
            #pragma unroll
            for (int q = 0; q < 4; ++q) acc[i][j][q] = 0.0f;

    // prologue: 2 chunks in flight (always commit to keep group counts exact)
    issue(0, 0); CP_COMMIT();
    if (nkt > 1) issue(1, 1);
    CP_COMMIT();

    for (int kt = 0; kt < nkt; ++kt) {
        __syncthreads();                              // WAR: buffer (kt+2)%3 free
        if (kt + 2 < nkt) issue(kt + 2, (kt + 2) % NSTG);
        CP_COMMIT();                                  // group kt+2 (possibly empty)
        CP_WAIT2();                                   // group kt complete
        __syncthreads();                              // all threads' copies visible

        uint32_t as = sbase + (kt % NSTG) * STAGE;
        uint32_t bs = as + ASZ;

        #pragma unroll
        for (int k16 = 0; k16 < 4; ++k16) {
            const int kb = k16 * 16;
            uint32_t af[4][4];
            #pragma unroll
            for (int i = 0; i < 4; ++i) {
                // lanes 0-15: rows m..m+15 at kb ; lanes 16-31: same rows at kb+8
                int mrow = wm * 64 + i * 16 + (lane & 15);
                ldm_x4(af[i], as + mrow * ROWA + (kb + (lane >> 4) * 8) * 2);
            }
            uint32_t bf[2][4];
            #pragma unroll
            for (int h = 0; h < 2; ++h) {
                // trans: lanes 0-15: k-rows kb..kb+15 at ncol ; 16-31: at ncol+8
                int krow = kb + (lane & 15);
                int ncol = wn * 32 + h * 16 + (lane >> 4) * 8;
                ldm_x4_t(bf[h], bs + krow * ROWB + ncol * 2);
            }
            #pragma unroll
            for (int i = 0; i < 4; ++i)
                #pragma unroll
                for (int j = 0; j < 4; ++j)
                    mma_f16(acc[i][j], af[i], &bf[j >> 1][(j & 1) * 2]);
        }
    }

    // ---------------- epilogue ----------------
    // C frag map (m16n8): c0,c1 -> (row r, cols 2cA,2cA+1); c2,c3 -> row r+8.
    const int r = lane >> 2, cA = lane & 3;

    if (C_IS_SCR) {   // GEMM1: +bias, gelu, fp16 store to g_h16
        __half* Cp = g_h16 + (size_t)b * M * N;
        #pragma unroll
        for (int j = 0; j < 4; ++j) {
            int col = n0 + wn * 32 + j * 8 + 2 * cA;
            float bv0 = bias[col], bv1 = bias[col + 1];
            #pragma unroll
            for (int i = 0; i < 4; ++i) {
                int row0 = m0 + wm * 64 + i * 16 + r;
                float v00 = acc[i][j][0] + bv0, v01 = acc[i][j][1] + bv1;
                float v10 = acc[i][j][2] + bv0, v11 = acc[i][j][3] + bv1;
                if (GELU) {
                    v00 = gelu_exact(v00); v01 = gelu_exact(v01);
                    v10 = gelu_exact(v10); v11 = gelu_exact(v11);
                }
                *reinterpret_cast<__half2*>(&Cp[(size_t)row0 * N + col])
                    = __floats2half2_rn(v00, v01);
                *reinterpret_cast<__half2*>(&Cp[(size_t)(row0 + 8) * N + col])
                    = __floats2half2_rn(v10, v11);
            }
        }
    } else {          // GEMM2: +bias, fp32 store to out
        float* Cp = Cout + (size_t)b * M * N;
        #pragma unroll
        for (int j = 0; j < 4; ++j) {
            int col = n0 + wn * 32 + j * 8 + 2 * cA;
            float bv0 = bias[col], bv1 = bias[col + 1];
            #pragma unroll
            for (int i = 0; i < 4; ++i) {
                int row0 = m0 + wm * 64 + i * 16 + r;
                *reinterpret_cast<float2*>(&Cp[(size_t)row0 * N + col])
                    = make_float2(acc[i][j][0] + bv0, acc[i][j][1] + bv1);
                *reinterpret_cast<float2*>(&Cp[(size_t)(row0 + 8) * N + col])
                    = make_float2(acc[i][j][2] + bv0, acc[i][j][3] + bv1);
            }
        }
    }
}

// ---------------- fp32 -> fp16 converters (device symbols referenced in-kernel) ----------------
__global__ void conv_x_kernel(const float4* __restrict__ src, int n4) {
    __half2* dst = reinterpret_cast<__half2*>(g_x16);
    int i = blockIdx.x * blockDim.x + threadIdx.x;
    int stride = gridDim.x * blockDim.x;
    for (; i < n4; i += stride) {
        float4 v = src[i];
        dst[2 * i]     = __floats2half2_rn(v.x, v.y);
        dst[2 * i + 1] = __floats2half2_rn(v.z, v.w);
    }
}
__global__ void conv_w_kernel(const float4* __restrict__ src, int n4, int which) {
    __half2* dst = reinterpret_cast<__half2*>(which ? g_w216 : g_w116);
    int i = blockIdx.x * blockDim.x + threadIdx.x;
    int stride = gridDim.x * blockDim.x;
    for (; i < n4; i += stride) {
        float4 v = src[i];
        dst[2 * i]     = __floats2half2_rn(v.x, v.y);
        dst[2 * i + 1] = __floats2half2_rn(v.z, v.w);
    }
}

// ---------------- launch ----------------
extern "C" void kernel_launch(void* const* d_in, const int* in_sizes, int n_in,
                              void* d_out, int out_size)
{
    const float* x  = (const float*)d_in[0];   // (64,32,32,512)
    const float* wg = (const float*)d_in[1];   // (512,5)
    const float* W1 = (const float*)d_in[2];   // (5,512,2048)
    const float* b1 = (const float*)d_in[3];   // (5,2048)
    const float* W2 = (const float*)d_in[4];   // (5,2048,512)
    const float* b2 = (const float*)d_in[5];   // (5,512)
    float* out = (float*)d_out;                // y (64*1024*512) then loss (1)

    cudaFuncSetAttribute(gemm_fp16<true, false, true>,
                         cudaFuncAttributeMaxDynamicSharedMemorySize, SMEM_BYTES);
    cudaFuncSetAttribute(gemm_fp16<false, true, false>,
                         cudaFuncAttributeMaxDynamicSharedMemorySize, SMEM_BYTES);

    // 0) fp32 -> fp16 conversions (x, W1, W2)
    const int xN4  = NB * HW * CC / 4;         // 8,388,608
    const int wN4  = EE * CC * HID / 4;        // 1,310,720
    conv_x_kernel<<<2048, 256>>>((const float4*)x, xN4);
    conv_w_kernel<<<1024, 256>>>((const float4*)W1, wN4, 0);
    conv_w_kernel<<<1024, 256>>>((const float4*)W2, wN4, 1);

    // 1) per-batch means (fp32, exact)
    xg_kernel<<<NB, CC>>>(x);

    // 2) gating + loss (loss is last element of out)
    gate_kernel<<<1, NB>>>(wg, out + (size_t)out_size - 1);

    // 3) h = gelu(x @ W1[e] + b1[e])  -> g_h16   (weights selected in-kernel)
    dim3 g1(HID / 128, HW / 128, NB);   // (16, 8, 64)
    gemm_fp16<true, false, true><<<g1, 256, SMEM_BYTES>>>(b1, nullptr, HW, HID, CC);

    // 4) y = h @ W2[e] + b2[e]        -> out
    dim3 g2(CC / 128, HW / 128, NB);    // (4, 8, 64)
    gemm_fp16<false, true, false><<<g2, 256, SMEM_BYTES>>>(b2, out, HW, CC, HID);
}

// round 15
// speedup vs baseline: 2.3131x; 1.2233x over previous
#include <cuda_runtime.h>
#include <cuda_fp16.h>
#include <cstdint>

// Problem shapes (fixed by the dataset)
#define NB   64      // batches
#define HW   1024    // tokens per batch (32*32)
#define CC   512     // channels
#define EE   5       // experts
#define HID  2048    // hidden

// ---------------- device scratch (no allocations allowed) ----------------
#define XSEG 8       // segments for xg partial sums
__device__ float  g_xgp[NB * XSEG * CC];           // partial channel sums
__device__ float  g_xg[NB * CC];
__device__ float  g_logits[NB * EE];
__device__ int    g_expert[NB];
__device__ __half g_x16[(size_t)NB * HW * CC];     // fp16 copy of x       (64 MB)
__device__ __half g_w116[(size_t)EE * CC * HID];   // fp16 copy of W1      (10.5 MB)
__device__ __half g_w216[(size_t)EE * HID * CC];   // fp16 copy of W2      (10.5 MB)
__device__ __half g_h16[(size_t)NB * HW * HID];    // fp16 h = gelu(xW1+b) (256 MB)

// ---------------- PTX helpers ----------------
__device__ __forceinline__ uint32_t smem_u32(const void* p) {
    uint32_t a;
    asm("{ .reg .u64 t; cvta.to.shared.u64 t, %1; cvt.u32.u64 %0, t; }" : "=r"(a) : "l"(p));
    return a;
}

__device__ __forceinline__ void cp_async16(uint32_t dst, const void* src) {
    asm volatile("cp.async.cg.shared.global [%0], [%1], 16;\n" :: "r"(dst), "l"(src));
}
#define CP_COMMIT() asm volatile("cp.async.commit_group;\n" ::: "memory")
#define CP_WAIT2()  asm volatile("cp.async.wait_group 2;\n" ::: "memory")

__device__ __forceinline__ void ldm_x4(uint32_t* r, uint32_t addr) {
    asm volatile("ldmatrix.sync.aligned.m8n8.x4.shared.b16 {%0,%1,%2,%3}, [%4];\n"
        : "=r"(r[0]), "=r"(r[1]), "=r"(r[2]), "=r"(r[3]) : "r"(addr));
}
__device__ __forceinline__ void ldm_x4_t(uint32_t* r, uint32_t addr) {
    asm volatile("ldmatrix.sync.aligned.m8n8.x4.trans.shared.b16 {%0,%1,%2,%3}, [%4];\n"
        : "=r"(r[0]), "=r"(r[1]), "=r"(r[2]), "=r"(r[3]) : "r"(addr));
}
__device__ __forceinline__ void mma_f16(float* d, const uint32_t* a, const uint32_t* b) {
    asm volatile(
        "mma.sync.aligned.m16n8k16.row.col.f32.f16.f16.f32 "
        "{%0,%1,%2,%3}, {%4,%5,%6,%7}, {%8,%9}, {%0,%1,%2,%3};\n"
        : "+f"(d[0]), "+f"(d[1]), "+f"(d[2]), "+f"(d[3])
        : "r"(a[0]), "r"(a[1]), "r"(a[2]), "r"(a[3]), "r"(b[0]), "r"(b[1]));
}

__device__ __forceinline__ float gelu_exact(float v) {
    return 0.5f * v * (1.0f + erff(v * 0.70710678118654752440f));
}

// ---------------- xg stage 1 + x->fp16 conversion (fused single pass over x) ----------------
// Each (b,seg,c) thread covers rows seg*128..seg*128+127 of channel c exactly once:
// sums for the mean AND stores the fp16 conversion (bit-identical to a separate
// conv pass; GEMM1 inputs unchanged).
__global__ void xg_part_kernel(const float* __restrict__ x) {
    int b   = blockIdx.x;               // batch
    int seg = blockIdx.y;               // HW segment
    int c   = threadIdx.x;              // channel
    size_t base = (size_t)b * HW * CC + (size_t)seg * (HW / XSEG) * CC + c;
    const float* p = x + base;
    __half* q = g_x16 + base;
    float s = 0.0f;
    #pragma unroll 8
    for (int i = 0; i < HW / XSEG; ++i) {
        float v = p[(size_t)i * CC];
        s += v;
        q[(size_t)i * CC] = __float2half_rn(v);
    }
    g_xgp[(b * XSEG + seg) * CC + c] = s;
}

// ---------------- xg stage 2: reduce partials (deterministic order) ----------------
__global__ void xg_reduce_kernel() {
    int b = blockIdx.x;
    int c = threadIdx.x;
    float s = 0.0f;
    #pragma unroll
    for (int seg = 0; seg < XSEG; ++seg) s += g_xgp[(b * XSEG + seg) * CC + c];
    g_xg[b * CC + c] = s * (1.0f / (float)HW);
}

// ---------------- gate logits: one block per batch, one warp per expert ----------------
__global__ void logits_kernel(const float* __restrict__ wg) {
    int b = blockIdx.x;
    int e = threadIdx.x >> 5;           // warp id = expert (blockDim = 160)
    int lane = threadIdx.x & 31;
    float s = 0.0f;
    for (int c = lane; c < CC; c += 32) s += g_xg[b * CC + c] * wg[c * EE + e];
    #pragma unroll
    for (int off = 16; off > 0; off >>= 1)
        s += __shfl_down_sync(0xFFFFFFFF, s, off);
    if (lane == 0) g_logits[b * EE + e] = s;
}

// ---------------- gate finalize: argmax + aux loss ----------------
// K=1: softmax over one logit == 1.0; importance == load == per-expert counts.
__global__ void gate_kernel(float* __restrict__ loss_out) {
    __shared__ int sh_e[NB];
    int b = threadIdx.x;
    if (b < NB) {
        float best = -3.4e38f; int bi = 0;
        #pragma unroll
        for (int e = 0; e < EE; ++e) {
            float s = g_logits[b * EE + e];
            if (s > best) { best = s; bi = e; }   // strict > == lowest-index tie-break (top_k)
        }
        sh_e[b] = bi;
        g_expert[b] = bi;
    }
    __syncthreads();
    if (b == 0) {
        float cnt[EE] = {0.f, 0.f, 0.f, 0.f, 0.f};
        for (int i = 0; i < NB; ++i) cnt[sh_e[i]] += 1.0f;
        float m = 0.0f;
        for (int e = 0; e < EE; ++e) m += cnt[e];
        m /= (float)EE;
        float var = 0.0f;
        for (int e = 0; e < EE; ++e) { float d = cnt[e] - m; var += d * d; }
        var /= (float)(EE - 1);                      // ddof=1
        float cv = (fabsf(m) < 1e-10f) ? 0.0f : var / (m * m + 1e-10f);
        float loss = 2.0f * cv;                      // importance == load
        if (loss > 1000.0f) loss = 1000.0f;
        *loss_out = loss;
    }
}

// ---------------- fp16 tensor-core GEMM with cp.async pipeline ----------------
// C[b] (MxN) = op( A[b] (MxK) @ W[expert[b]] (KxN) + bias[expert[b]] )
// CTA tile 128x128, 8 warps (2x4), warp tile 64x32, K-chunk 64, fragments m16n8k16.
// 3-stage cp.async pipeline (fp16 operands in gmem), ldmatrix fragment loads.
// NOTE: all __device__ arrays are referenced ONLY inside device code — passing
// them as kernel args from host yields the host shadow address (the R7 bug).
// Register budget: 128/thread == 65536/2/256, the exact 2-CTA/SM ceiling.
#define KC    64                 // K elements per chunk
#define ROWA  144                // A smem row bytes (64 halves + 8 pad halves)
#define ROWB  272                // B smem row bytes (128 halves + 8 pad halves)
#define ASZ   (128 * ROWA)       // 18432
#define BSZ   (KC * ROWB)        // 17408
#define STAGE (ASZ + BSZ)        // 35840
#define NSTG  3
#define SMEM_BYTES (NSTG * STAGE)   // 107520 -> 2 CTAs/SM = 215040 B

template <bool GELU, bool A_IS_SCR, bool C_IS_SCR>
__global__ __launch_bounds__(256, 2)
void gemm_fp16(const float* __restrict__ biasbase, float* __restrict__ Cout,
               int M, int N, int K)
{
    extern __shared__ char smem[];
    const uint32_t sbase = smem_u32(smem);

    const int b = blockIdx.z;
    const int e = g_expert[b];
    const __half* A    = (A_IS_SCR ? g_h16 : g_x16) + (size_t)b * M * K;
    const __half* Bm   = (C_IS_SCR ? g_w116 : g_w216) + (size_t)e * K * N;
    const float*  bias = biasbase + (size_t)e * N;

    const int m0 = blockIdx.y * 128, n0 = blockIdx.x * 128;
    const int tid = threadIdx.x, lane = tid & 31, warp = tid >> 5;
    const int wm = warp >> 2, wn = warp & 3;          // 2x4 warp grid, warp tile 64x32

    const int nkt = K / KC;

    // stage chunk kt into buffer s (8 x cp.async 16B per thread)
    auto issue = [&](int kt, int s) {
        uint32_t as = sbase + s * STAGE;
        uint32_t bs = as + ASZ;
        #pragma unroll
        for (int i = 0; i < 4; ++i) {                 // A: 128 rows x 8 chunks
            int idx = tid + i * 256;
            int row = idx >> 3, cg = idx & 7;
            cp_async16(as + row * ROWA + cg * 16,
                       A + (size_t)(m0 + row) * K + kt * KC + cg * 8);
        }
        #pragma unroll
        for (int i = 0; i < 4; ++i) {                 // B: 64 k-rows x 16 chunks
            int idx = tid + i * 256;
            int row = idx >> 4, cg = idx & 15;
            cp_async16(bs + row * ROWB + cg * 16,
                       Bm + (size_t)(kt * KC + row) * N + n0 + cg * 8);
        }
    };

    float acc[4][4][4];
    #pragma unroll
    for (int i = 0; i < 4; ++i)
        #pragma unroll
        for (int j = 0; j < 4; ++j)
            #pragma unroll
            for (int q = 0; q < 4; ++q) acc[i][j][q] = 0.0f;

    // prologue: 2 chunks in flight (always commit to keep group counts exact)
    issue(0, 0); CP_COMMIT();
    if (nkt > 1) issue(1, 1);
    CP_COMMIT();

    for (int kt = 0; kt < nkt; ++kt) {
        __syncthreads();                              // WAR: buffer (kt+2)%3 free
        if (kt + 2 < nkt) issue(kt + 2, (kt + 2) % NSTG);
        CP_COMMIT();                                  // group kt+2 (possibly empty)
        CP_WAIT2();                                   // group kt complete
        __syncthreads();                              // all threads' copies visible

        uint32_t as = sbase + (kt % NSTG) * STAGE;
        uint32_t bs = as + ASZ;

        #pragma unroll
        for (int k16 = 0; k16 < 4; ++k16) {
            const int kb = k16 * 16;
            uint32_t af[4][4];
            #pragma unroll
            for (int i = 0; i < 4; ++i) {
                // lanes 0-15: rows m..m+15 at kb ; lanes 16-31: same rows at kb+8
                int mrow = wm * 64 + i * 16 + (lane & 15);
                ldm_x4(af[i], as + mrow * ROWA + (kb + (lane >> 4) * 8) * 2);
            }
            uint32_t bf[2][4];
            #pragma unroll
            for (int h = 0; h < 2; ++h) {
                // trans: lanes 0-15: k-rows kb..kb+15 at ncol ; 16-31: at ncol+8
                int krow = kb + (lane & 15);
                int ncol = wn * 32 + h * 16 + (lane >> 4) * 8;
                ldm_x4_t(bf[h], bs + krow * ROWB + ncol * 2);
            }
            #pragma unroll
            for (int i = 0; i < 4; ++i)
                #pragma unroll
                for (int j = 0; j < 4; ++j)
                    mma_f16(acc[i][j], af[i], &bf[j >> 1][(j & 1) * 2]);
        }
    }

    // ---------------- epilogue ----------------
    // C frag map (m16n8): c0,c1 -> (row r, cols 2cA,2cA+1); c2,c3 -> row r+8.
    const int r = lane >> 2, cA = lane & 3;

    if (C_IS_SCR) {   // GEMM1: +bias, gelu, fp16 store to g_h16
        __half* Cp = g_h16 + (size_t)b * M * N;
        #pragma unroll
        for (int j = 0; j < 4; ++j) {
            int col = n0 + wn * 32 + j * 8 + 2 * cA;
            float bv0 = bias[col], bv1 = bias[col + 1];
            #pragma unroll
            for (int i = 0; i < 4; ++i) {
                int row0 = m0 + wm * 64 + i * 16 + r;
                float v00 = acc[i][j][0] + bv0, v01 = acc[i][j][1] + bv1;
                float v10 = acc[i][j][2] + bv0, v11 = acc[i][j][3] + bv1;
                if (GELU) {
                    v00 = gelu_exact(v00); v01 = gelu_exact(v01);
                    v10 = gelu_exact(v10); v11 = gelu_exact(v11);
                }
                *reinterpret_cast<__half2*>(&Cp[(size_t)row0 * N + col])
                    = __floats2half2_rn(v00, v01);
                *reinterpret_cast<__half2*>(&Cp[(size_t)(row0 + 8) * N + col])
                    = __floats2half2_rn(v10, v11);
            }
        }
    } else {          // GEMM2: +bias, fp32 store to out
        float* Cp = Cout + (size_t)b * M * N;
        #pragma unroll
        for (int j = 0; j < 4; ++j) {
            int col = n0 + wn * 32 + j * 8 + 2 * cA;
            float bv0 = bias[col], bv1 = bias[col + 1];
            #pragma unroll
            for (int i = 0; i < 4; ++i) {
                int row0 = m0 + wm * 64 + i * 16 + r;
                *reinterpret_cast<float2*>(&Cp[(size_t)row0 * N + col])
                    = make_float2(acc[i][j][0] + bv0, acc[i][j][1] + bv1);
                *reinterpret_cast<float2*>(&Cp[(size_t)(row0 + 8) * N + col])
                    = make_float2(acc[i][j][2] + bv0, acc[i][j][3] + bv1);
            }
        }
    }
}

// ---------------- fp32 -> fp16 weight converter (device symbols referenced in-kernel) ----------------
__global__ void conv_w_kernel(const float4* __restrict__ src, int n4, int which) {
    __half2* dst = reinterpret_cast<__half2*>(which ? g_w216 : g_w116);
    int i = blockIdx.x * blockDim.x + threadIdx.x;
    int stride = gridDim.x * blockDim.x;
    for (; i < n4; i += stride) {
        float4 v = src[i];
        dst[2 * i]     = __floats2half2_rn(v.x, v.y);
        dst[2 * i + 1] = __floats2half2_rn(v.z, v.w);
    }
}

// ---------------- launch ----------------
// GEMMs placed last so the ncu capture window (skip ~5 launches) tends to land
// on a GEMM (or at worst conv_w, also actionable).
extern "C" void kernel_launch(void* const* d_in, const int* in_sizes, int n_in,
                              void* d_out, int out_size)
{
    const float* x  = (const float*)d_in[0];   // (64,32,32,512)
    const float* wg = (const float*)d_in[1];   // (512,5)
    const float* W1 = (const float*)d_in[2];   // (5,512,2048)
    const float* b1 = (const float*)d_in[3];   // (5,2048)
    const float* W2 = (const float*)d_in[4];   // (5,2048,512)
    const float* b2 = (const float*)d_in[5];   // (5,512)
    float* out = (float*)d_out;                // y (64*1024*512) then loss (1)

    cudaFuncSetAttribute(gemm_fp16<true, false, true>,
                         cudaFuncAttributeMaxDynamicSharedMemorySize, SMEM_BYTES);
    cudaFuncSetAttribute(gemm_fp16<false, true, false>,
                         cudaFuncAttributeMaxDynamicSharedMemorySize, SMEM_BYTES);

    // 1) fused xg partials + x->fp16, then reduce -> logits -> argmax+loss
    dim3 gx(NB, XSEG);
    xg_part_kernel<<<gx, CC>>>(x);                       // launch 1 (also writes g_x16)
    xg_reduce_kernel<<<NB, CC>>>();                      // launch 2
    logits_kernel<<<NB, EE * 32>>>(wg);                  // launch 3
    gate_kernel<<<1, NB>>>(out + (size_t)out_size - 1);  // launch 4

    // 2) fp32 -> fp16 weight conversions
    const int wN4 = EE * CC * HID / 4;         // 1,310,720
    conv_w_kernel<<<1024, 256>>>((const float4*)W1, wN4, 0); // launch 5
    conv_w_kernel<<<1024, 256>>>((const float4*)W2, wN4, 1); // launch 6

    // 3) h = gelu(x @ W1[e] + b1[e])  -> g_h16
    dim3 g1(HID / 128, HW / 128, NB);   // (16, 8, 64)
    gemm_fp16<true, false, true><<<g1, 256, SMEM_BYTES>>>(b1, nullptr, HW, HID, CC);

    // 4) y = h @ W2[e] + b2[e]        -> out
    dim3 g2(CC / 128, HW / 128, NB);    // (4, 8, 64)
    gemm_fp16<false, true, false><<<g2, 256, SMEM_BYTES>>>(b2, out, HW, CC, HID);
}

// round 17
// speedup vs baseline: 2.3284x; 1.0066x over previous
#include <cuda_runtime.h>
#include <cuda_fp16.h>
#include <cstdint>

// Problem shapes (fixed by the dataset)
#define NB   64      // batches
#define HW   1024    // tokens per batch (32*32)
#define CC   512     // channels
#define EE   5       // experts
#define HID  2048    // hidden

// ---------------- device scratch (no allocations allowed) ----------------
#define XSEG 8       // segments for xg partial sums
__device__ float  g_xgp[NB * XSEG * CC];           // partial channel sums
__device__ float  g_logits[NB * EE];
__device__ int    g_expert[NB];
__device__ __half g_x16[(size_t)NB * HW * CC];     // fp16 copy of x       (64 MB)
__device__ __half g_w116[(size_t)EE * CC * HID];   // fp16 copy of W1      (10.5 MB)
__device__ __half g_w216[(size_t)EE * HID * CC];   // fp16 copy of W2      (10.5 MB)
__device__ __half g_h16[(size_t)NB * HW * HID];    // fp16 h = gelu(xW1+b) (256 MB)

// ---------------- PTX helpers ----------------
__device__ __forceinline__ uint32_t smem_u32(const void* p) {
    uint32_t a;
    asm("{ .reg .u64 t; cvta.to.shared.u64 t, %1; cvt.u32.u64 %0, t; }" : "=r"(a) : "l"(p));
    return a;
}

__device__ __forceinline__ void cp_async16(uint32_t dst, const void* src) {
    asm volatile("cp.async.cg.shared.global [%0], [%1], 16;\n" :: "r"(dst), "l"(src));
}
#define CP_COMMIT() asm volatile("cp.async.commit_group;\n" ::: "memory")
#define CP_WAIT2()  asm volatile("cp.async.wait_group 2;\n" ::: "memory")

__device__ __forceinline__ void ldm_x4(uint32_t* r, uint32_t addr) {
    asm volatile("ldmatrix.sync.aligned.m8n8.x4.shared.b16 {%0,%1,%2,%3}, [%4];\n"
        : "=r"(r[0]), "=r"(r[1]), "=r"(r[2]), "=r"(r[3]) : "r"(addr));
}
__device__ __forceinline__ void ldm_x4_t(uint32_t* r, uint32_t addr) {
    asm volatile("ldmatrix.sync.aligned.m8n8.x4.trans.shared.b16 {%0,%1,%2,%3}, [%4];\n"
        : "=r"(r[0]), "=r"(r[1]), "=r"(r[2]), "=r"(r[3]) : "r"(addr));
}
__device__ __forceinline__ void mma_f16(float* d, const uint32_t* a, const uint32_t* b) {
    asm volatile(
        "mma.sync.aligned.m16n8k16.row.col.f32.f16.f16.f32 "
        "{%0,%1,%2,%3}, {%4,%5,%6,%7}, {%8,%9}, {%0,%1,%2,%3};\n"
        : "+f"(d[0]), "+f"(d[1]), "+f"(d[2]), "+f"(d[3])
        : "r"(a[0]), "r"(a[1]), "r"(a[2]), "r"(a[3]), "r"(b[0]), "r"(b[1]));
}

__device__ __forceinline__ float gelu_exact(float v) {
    return 0.5f * v * (1.0f + erff(v * 0.70710678118654752440f));
}

// ---------------- launch 1: xg partials + x->fp16 (fused single pass over x) ----------------
__global__ void xg_part_kernel(const float* __restrict__ x) {
    int b   = blockIdx.x;               // batch
    int seg = blockIdx.y;               // HW segment
    int c   = threadIdx.x;              // channel
    size_t base = (size_t)b * HW * CC + (size_t)seg * (HW / XSEG) * CC + c;
    const float* p = x + base;
    __half* q = g_x16 + base;
    float s = 0.0f;
    #pragma unroll 8
    for (int i = 0; i < HW / XSEG; ++i) {
        float v = p[(size_t)i * CC];
        s += v;
        q[(size_t)i * CC] = __float2half_rn(v);
    }
    g_xgp[(b * XSEG + seg) * CC + c] = s;
}

// ---------------- launch 2: reduce partials + logits (fused; one block per batch) ----------------
// Phase A: thread c reduces 8 partials (deterministic order) -> smem xg row.
// Phase B: warps 0..EE-1 (one per expert) do the lane-strided dot + shfl tree.
// Numerically identical to the previous xg_reduce + logits pair.
__global__ void xg_reduce_logits_kernel(const float* __restrict__ wg) {
    __shared__ float sxg[CC];
    int b = blockIdx.x;
    int c = threadIdx.x;                 // blockDim = 512
    float s = 0.0f;
    #pragma unroll
    for (int seg = 0; seg < XSEG; ++seg) s += g_xgp[(b * XSEG + seg) * CC + c];
    sxg[c] = s * (1.0f / (float)HW);
    __syncthreads();
    int warp = c >> 5, lane = c & 31;
    if (warp < EE) {
        float t = 0.0f;
        for (int cc = lane; cc < CC; cc += 32) t += sxg[cc] * wg[cc * EE + warp];
        #pragma unroll
        for (int off = 16; off > 0; off >>= 1)
            t += __shfl_down_sync(0xFFFFFFFF, t, off);
        if (lane == 0) g_logits[b * EE + warp] = t;
    }
}

// ---------------- launch 3: gate finalize (block 0) + weight conversions (blocks 1+) ----------------
// K=1: softmax over one logit == 1.0; importance == load == per-expert counts.
__global__ void gate_conv_kernel(const float4* __restrict__ W1f, const float4* __restrict__ W2f,
                                 int n4each, float* __restrict__ loss_out) {
    if (blockIdx.x == 0) {
        __shared__ int sh_e[NB];
        int b = threadIdx.x;
        if (b < NB) {
            float best = -3.4e38f; int bi = 0;
            #pragma unroll
            for (int e = 0; e < EE; ++e) {
                float s = g_logits[b * EE + e];
                if (s > best) { best = s; bi = e; }   // strict > == lowest-index tie-break (top_k)
            }
            sh_e[b] = bi;
            g_expert[b] = bi;
        }
        __syncthreads();
        if (b == 0) {
            float cnt[EE] = {0.f, 0.f, 0.f, 0.f, 0.f};
            for (int i = 0; i < NB; ++i) cnt[sh_e[i]] += 1.0f;
            float m = 0.0f;
            for (int e = 0; e < EE; ++e) m += cnt[e];
            m /= (float)EE;
            float var = 0.0f;
            for (int e = 0; e < EE; ++e) { float d = cnt[e] - m; var += d * d; }
            var /= (float)(EE - 1);                      // ddof=1
            float cv = (fabsf(m) < 1e-10f) ? 0.0f : var / (m * m + 1e-10f);
            float loss = 2.0f * cv;                      // importance == load
            if (loss > 1000.0f) loss = 1000.0f;
            *loss_out = loss;
        }
        return;
    }
    // blocks 1..gridDim-1: convert W1 and W2 (grid-stride, deterministic)
    __half2* d1 = reinterpret_cast<__half2*>(g_w116);
    __half2* d2 = reinterpret_cast<__half2*>(g_w216);
    int i = (blockIdx.x - 1) * blockDim.x + threadIdx.x;
    int stride = (gridDim.x - 1) * blockDim.x;
    for (; i < n4each; i += stride) {
        float4 v = W1f[i];
        d1[2 * i]     = __floats2half2_rn(v.x, v.y);
        d1[2 * i + 1] = __floats2half2_rn(v.z, v.w);
        float4 w = W2f[i];
        d2[2 * i]     = __floats2half2_rn(w.x, w.y);
        d2[2 * i + 1] = __floats2half2_rn(w.z, w.w);
    }
}

// ---------------- fp16 tensor-core GEMM with cp.async pipeline ----------------
// C[b] (MxN) = op( A[b] (MxK) @ W[expert[b]] (KxN) + bias[expert[b]] )
// CTA tile 128x128, 8 warps (2x4), warp tile 64x32, K-chunk 64, fragments m16n8k16.
// 3-stage cp.async pipeline (fp16 operands in gmem), ldmatrix fragment loads.
// NOTE: all __device__ arrays are referenced ONLY inside device code — passing
// them as kernel args from host yields the host shadow address (the R7 bug).
// Register budget: 128/thread == 65536/2/256, the exact 2-CTA/SM ceiling.
#define KC    64                 // K elements per chunk
#define ROWA  144                // A smem row bytes (64 halves + 8 pad halves)
#define ROWB  272                // B smem row bytes (128 halves + 8 pad halves)
#define ASZ   (128 * ROWA)       // 18432
#define BSZ   (KC * ROWB)        // 17408
#define STAGE (ASZ + BSZ)        // 35840
#define NSTG  3
#define SMEM_BYTES (NSTG * STAGE)   // 107520 -> 2 CTAs/SM = 215040 B

template <bool GELU, bool A_IS_SCR, bool C_IS_SCR>
__global__ __launch_bounds__(256, 2)
void gemm_fp16(const float* __restrict__ biasbase, float* __restrict__ Cout,
               int M, int N, int K)
{
    extern __shared__ char smem[];
    const uint32_t sbase = smem_u32(smem);

    const int b = blockIdx.z;
    const int e = g_expert[b];
    const __half* A    = (A_IS_SCR ? g_h16 : g_x16) + (size_t)b * M * K;
    const __half* Bm   = (C_IS_SCR ? g_w116 : g_w216) + (size_t)e * K * N;
    const float*  bias = biasbase + (size_t)e * N;

    const int m0 = blockIdx.y * 128, n0 = blockIdx.x * 128;
    const int tid = threadIdx.x, lane = tid & 31, warp = tid >> 5;
    const int wm = warp >> 2, wn = warp & 3;          // 2x4 warp grid, warp tile 64x32

    const int nkt = K / KC;

    // stage chunk kt into buffer s (8 x cp.async 16B per thread)
    auto issue = [&](int kt, int s) {
        uint32_t as = sbase + s * STAGE;
        uint32_t bs = as + ASZ;
        #pragma unroll
        for (int i = 0; i < 4; ++i) {                 // A: 128 rows x 8 chunks
            int idx = tid + i * 256;
            int row = idx >> 3, cg = idx & 7;
            cp_async16(as + row * ROWA + cg * 16,
                       A + (size_t)(m0 + row) * K + kt * KC + cg * 8);
        }
        #pragma unroll
        for (int i = 0; i < 4; ++i) {                 // B: 64 k-rows x 16 chunks
            int idx = tid + i * 256;
            int row = idx >> 4, cg = idx & 15;
            cp_async16(bs + row * ROWB + cg * 16,
                       Bm + (size_t)(kt * KC + row) * N + n0 + cg * 8);
        }
    };

    float acc[4][4][4];
    #pragma unroll
    for (int i = 0; i < 4; ++i)
        #pragma unroll
        for (int j = 0; j < 4; ++j)
            #pragma unroll
            for (int q = 0; q < 4; ++q) acc[i][j][q] = 0.0f;

    // prologue: 2 chunks in flight (always commit to keep group counts exact)
    issue(0, 0); CP_COMMIT();
    if (nkt > 1) issue(1, 1);
    CP_COMMIT();

    for (int kt = 0; kt < nkt; ++kt) {
        __syncthreads();                              // WAR: buffer (kt+2)%3 free
        if (kt + 2 < nkt) issue(kt + 2, (kt + 2) % NSTG);
        CP_COMMIT();                                  // group kt+2 (possibly empty)
        CP_WAIT2();                                   // group kt complete
        __syncthreads();                              // all threads' copies visible

        uint32_t as = sbase + (kt % NSTG) * STAGE;
        uint32_t bs = as + ASZ;

        #pragma unroll
        for (int k16 = 0; k16 < 4; ++k16) {
            const int kb = k16 * 16;
            uint32_t af[4][4];
            #pragma unroll
            for (int i = 0; i < 4; ++i) {
                // lanes 0-15: rows m..m+15 at kb ; lanes 16-31: same rows at kb+8
                int mrow = wm * 64 + i * 16 + (lane & 15);
                ldm_x4(af[i], as + mrow * ROWA + (kb + (lane >> 4) * 8) * 2);
            }
            uint32_t bf[2][4];
            #pragma unroll
            for (int h = 0; h < 2; ++h) {
                // trans: lanes 0-15: k-rows kb..kb+15 at ncol ; 16-31: at ncol+8
                int krow = kb + (lane & 15);
                int ncol = wn * 32 + h * 16 + (lane >> 4) * 8;
                ldm_x4_t(bf[h], bs + krow * ROWB + ncol * 2);
            }
            #pragma unroll
            for (int i = 0; i < 4; ++i)
                #pragma unroll
                for (int j = 0; j < 4; ++j)
                    mma_f16(acc[i][j], af[i], &bf[j >> 1][(j & 1) * 2]);
        }
    }

    // ---------------- epilogue ----------------
    // C frag map (m16n8): c0,c1 -> (row r, cols 2cA,2cA+1); c2,c3 -> row r+8.
    const int r = lane >> 2, cA = lane & 3;

    if (C_IS_SCR) {   // GEMM1: +bias, gelu, fp16 store to g_h16
        __half* Cp = g_h16 + (size_t)b * M * N;
        #pragma unroll
        for (int j = 0; j < 4; ++j) {
            int col = n0 + wn * 32 + j * 8 + 2 * cA;
            float bv0 = bias[col], bv1 = bias[col + 1];
            #pragma unroll
            for (int i = 0; i < 4; ++i) {
                int row0 = m0 + wm * 64 + i * 16 + r;
                float v00 = acc[i][j][0] + bv0, v01 = acc[i][j][1] + bv1;
                float v10 = acc[i][j][2] + bv0, v11 = acc[i][j][3] + bv1;
                if (GELU) {
                    v00 = gelu_exact(v00); v01 = gelu_exact(v01);
                    v10 = gelu_exact(v10); v11 = gelu_exact(v11);
                }
                *reinterpret_cast<__half2*>(&Cp[(size_t)row0 * N + col])
                    = __floats2half2_rn(v00, v01);
                *reinterpret_cast<__half2*>(&Cp[(size_t)(row0 + 8) * N + col])
                    = __floats2half2_rn(v10, v11);
            }
        }
    } else {          // GEMM2: +bias, fp32 store to out
        float* Cp = Cout + (size_t)b * M * N;
        #pragma unroll
        for (int j = 0; j < 4; ++j) {
            int col = n0 + wn * 32 + j * 8 + 2 * cA;
            float bv0 = bias[col], bv1 = bias[col + 1];
            #pragma unroll
            for (int i = 0; i < 4; ++i) {
                int row0 = m0 + wm * 64 + i * 16 + r;
                *reinterpret_cast<float2*>(&Cp[(size_t)row0 * N + col])
                    = make_float2(acc[i][j][0] + bv0, acc[i][j][1] + bv1);
                *reinterpret_cast<float2*>(&Cp[(size_t)(row0 + 8) * N + col])
                    = make_float2(acc[i][j][2] + bv0, acc[i][j][3] + bv1);
            }
        }
    }
}

// ---------------- launch ----------------
// The ncu capture window lands on the 4th launch (observed R1/R9/R15), so the
// sequence is arranged to put GEMM1 there: xg_part, xg_reduce_logits,
// gate+conv fused, GEMM1, GEMM2.
extern "C" void kernel_launch(void* const* d_in, const int* in_sizes, int n_in,
                              void* d_out, int out_size)
{
    const float* x  = (const float*)d_in[0];   // (64,32,32,512)
    const float* wg = (const float*)d_in[1];   // (512,5)
    const float* W1 = (const float*)d_in[2];   // (5,512,2048)
    const float* b1 = (const float*)d_in[3];   // (5,2048)
    const float* W2 = (const float*)d_in[4];   // (5,2048,512)
    const float* b2 = (const float*)d_in[5];   // (5,512)
    float* out = (float*)d_out;                // y (64*1024*512) then loss (1)

    cudaFuncSetAttribute(gemm_fp16<true, false, true>,
                         cudaFuncAttributeMaxDynamicSharedMemorySize, SMEM_BYTES);
    cudaFuncSetAttribute(gemm_fp16<false, true, false>,
                         cudaFuncAttributeMaxDynamicSharedMemorySize, SMEM_BYTES);

    // 1) fused xg partials + x->fp16
    dim3 gx(NB, XSEG);
    xg_part_kernel<<<gx, CC>>>(x);                               // launch 1

    // 2) fused reduce + logits (one block per batch)
    xg_reduce_logits_kernel<<<NB, CC>>>(wg);                     // launch 2

    // 3) fused gate finalize + W1/W2 -> fp16 conversion
    const int wN4 = EE * CC * HID / 4;         // 1,310,720 float4 per weight tensor
    gate_conv_kernel<<<1025, 256>>>((const float4*)W1, (const float4*)W2,
                                    wN4, out + (size_t)out_size - 1);  // launch 3

    // 4) h = gelu(x @ W1[e] + b1[e])  -> g_h16    [ncu window lands here]
    dim3 g1(HID / 128, HW / 128, NB);   // (16, 8, 64)
    gemm_fp16<true, false, true><<<g1, 256, SMEM_BYTES>>>(b1, nullptr, HW, HID, CC);

    // 5) y = h @ W2[e] + b2[e]        -> out
    dim3 g2(CC / 128, HW / 128, NB);    // (4, 8, 64)
    gemm_fp16<false, true, false><<<g2, 256, SMEM_BYTES>>>(b2, out, HW, CC, HID);
}